// round 1
// baseline (speedup 1.0000x reference)
#include <cuda_runtime.h>
#include <cuda_bf16.h>

// Problem constants (shapes fixed by the dataset).
#define B_   2
#define S_   3072
#define D_   2048
#define H_   16
#define HD_  128
#define M_   (B_ * S_)     // 6144 tokens

// ---------------------------------------------------------------------------
// Scratch (static device globals; no allocation anywhere)
// ---------------------------------------------------------------------------
__device__ float g_q[M_ * D_];
__device__ float g_k[M_ * D_];
__device__ float g_v[M_ * D_];
__device__ float g_attn[M_ * D_];

// ---------------------------------------------------------------------------
// GEMM:  O[m,n] = sum_k X[m,k] * W[n,k] + bias[n]
// X: (M_, 2048) row-major, W: (2048, 2048) row-major, O: (M_, 2048)
// 128x128 block tile, BK=16, 256 threads, 8x8 per-thread micro-tile.
// ---------------------------------------------------------------------------
__global__ void __launch_bounds__(256, 2) gemm_bias(
    const float* __restrict__ X,
    const float* __restrict__ W,
    const float* __restrict__ bias,
    float*       __restrict__ O)
{
    __shared__ float As[16 * 132];   // As[kk][m], padded stride 132
    __shared__ float Bs[16 * 132];   // Bs[kk][n]

    const int bm  = blockIdx.y * 128;
    const int bn  = blockIdx.x * 128;
    const int tid = threadIdx.x;
    const int tx  = tid & 15;        // n-group
    const int ty  = tid >> 4;        // m-group

    const int f0 = tid;
    const int f1 = tid + 256;
    const int r0 = f0 >> 2, c0 = (f0 & 3) * 4;
    const int r1 = f1 >> 2, c1 = (f1 & 3) * 4;

    float acc[8][8];
    #pragma unroll
    for (int i = 0; i < 8; i++)
        #pragma unroll
        for (int j = 0; j < 8; j++) acc[i][j] = 0.0f;

    for (int kt = 0; kt < D_; kt += 16) {
        float4 a0 = *(const float4*)(X + (size_t)(bm + r0) * D_ + kt + c0);
        float4 a1 = *(const float4*)(X + (size_t)(bm + r1) * D_ + kt + c1);
        float4 w0 = *(const float4*)(W + (size_t)(bn + r0) * D_ + kt + c0);
        float4 w1 = *(const float4*)(W + (size_t)(bn + r1) * D_ + kt + c1);

        __syncthreads();   // previous tile fully consumed
        As[(c0 + 0) * 132 + r0] = a0.x;
        As[(c0 + 1) * 132 + r0] = a0.y;
        As[(c0 + 2) * 132 + r0] = a0.z;
        As[(c0 + 3) * 132 + r0] = a0.w;
        As[(c1 + 0) * 132 + r1] = a1.x;
        As[(c1 + 1) * 132 + r1] = a1.y;
        As[(c1 + 2) * 132 + r1] = a1.z;
        As[(c1 + 3) * 132 + r1] = a1.w;
        Bs[(c0 + 0) * 132 + r0] = w0.x;
        Bs[(c0 + 1) * 132 + r0] = w0.y;
        Bs[(c0 + 2) * 132 + r0] = w0.z;
        Bs[(c0 + 3) * 132 + r0] = w0.w;
        Bs[(c1 + 0) * 132 + r1] = w1.x;
        Bs[(c1 + 1) * 132 + r1] = w1.y;
        Bs[(c1 + 2) * 132 + r1] = w1.z;
        Bs[(c1 + 3) * 132 + r1] = w1.w;
        __syncthreads();

        #pragma unroll
        for (int kk = 0; kk < 16; kk++) {
            float4 av0 = *(const float4*)(As + kk * 132 + ty * 8);
            float4 av1 = *(const float4*)(As + kk * 132 + ty * 8 + 4);
            float4 bv0 = *(const float4*)(Bs + kk * 132 + tx * 8);
            float4 bv1 = *(const float4*)(Bs + kk * 132 + tx * 8 + 4);
            float a[8] = {av0.x, av0.y, av0.z, av0.w, av1.x, av1.y, av1.z, av1.w};
            float bb[8] = {bv0.x, bv0.y, bv0.z, bv0.w, bv1.x, bv1.y, bv1.z, bv1.w};
            #pragma unroll
            for (int i = 0; i < 8; i++)
                #pragma unroll
                for (int j = 0; j < 8; j++)
                    acc[i][j] = fmaf(a[i], bb[j], acc[i][j]);
        }
    }

    float4 bv0 = *(const float4*)(bias + bn + tx * 8);
    float4 bv1 = *(const float4*)(bias + bn + tx * 8 + 4);
    const float bb[8] = {bv0.x, bv0.y, bv0.z, bv0.w, bv1.x, bv1.y, bv1.z, bv1.w};

    #pragma unroll
    for (int i = 0; i < 8; i++) {
        float* op = O + (size_t)(bm + ty * 8 + i) * D_ + bn + tx * 8;
        float4 o0, o1;
        o0.x = acc[i][0] + bb[0];
        o0.y = acc[i][1] + bb[1];
        o0.z = acc[i][2] + bb[2];
        o0.w = acc[i][3] + bb[3];
        o1.x = acc[i][4] + bb[4];
        o1.y = acc[i][5] + bb[5];
        o1.z = acc[i][6] + bb[6];
        o1.w = acc[i][7] + bb[7];
        *(float4*)(op)     = o0;
        *(float4*)(op + 4) = o1;
    }
}

// ---------------------------------------------------------------------------
// Fused RMSNorm + interleaved RoPE, in place, for Q (blockIdx.y==0) and K (==1)
// One block per (token, tensor); 256 threads, thread t owns dims [8t, 8t+8).
// ---------------------------------------------------------------------------
__global__ void __launch_bounds__(256) rms_rope(
    float* __restrict__ Tq, float* __restrict__ Tk,
    const float* __restrict__ gq, const float* __restrict__ gk,
    const float* __restrict__ rot)
{
    const int token = blockIdx.x;        // b*S + s
    const int s     = token % S_;
    float*       T  = (blockIdx.y == 0) ? Tq : Tk;
    const float* g  = (blockIdx.y == 0) ? gq : gk;
    const int t     = threadIdx.x;

    float* row = T + (size_t)token * D_;
    float4 v0 = *(const float4*)(row + t * 8);
    float4 v1 = *(const float4*)(row + t * 8 + 4);
    float x[8] = {v0.x, v0.y, v0.z, v0.w, v1.x, v1.y, v1.z, v1.w};

    float ss = 0.0f;
    #pragma unroll
    for (int i = 0; i < 8; i++) ss += x[i] * x[i];
    #pragma unroll
    for (int o = 16; o; o >>= 1) ss += __shfl_xor_sync(0xffffffffu, ss, o);

    __shared__ float red[8];
    __shared__ float rs_s;
    if ((t & 31) == 0) red[t >> 5] = ss;
    __syncthreads();
    if (t == 0) {
        float tot = 0.0f;
        #pragma unroll
        for (int i = 0; i < 8; i++) tot += red[i];
        rs_s = rsqrtf(tot * (1.0f / (float)D_) + 1e-6f);
    }
    __syncthreads();
    const float rs = rs_s;

    const float* rc = rot + (size_t)s * (2 * HD_);
    float out[8];
    #pragma unroll
    for (int j = 0; j < 4; j++) {
        const int d0 = t * 8 + 2 * j;          // even dim
        const int i2 = d0 & (HD_ - 1);         // 2*i within the head
        const float c  = rc[i2];               // cos[2i]
        const float sn = rc[HD_ + i2 + 1];     // sin[2i+1]
        const float x1 = x[2 * j]     * rs * g[d0];
        const float x2 = x[2 * j + 1] * rs * g[d0 + 1];
        out[2 * j]     = x1 * c - x2 * sn;
        out[2 * j + 1] = x1 * sn + x2 * c;
    }
    float4 o0 = {out[0], out[1], out[2], out[3]};
    float4 o1 = {out[4], out[5], out[6], out[7]};
    *(float4*)(row + t * 8)     = o0;
    *(float4*)(row + t * 8 + 4) = o1;
}

// ---------------------------------------------------------------------------
// Flash-style SDPA, fp32.  Block = 64 queries of one (b,h).  Key tiles of 64.
// Per-row kv_len: s < hist -> hist, else S (hist computed from device scalars).
// Thread grid 16x16; each thread owns a 4(q) x 4(k) score micro-tile and a
// 4(q) x 8(d) output micro-tile.  P goes through smem for the PV transpose.
// ---------------------------------------------------------------------------
#define BM 64
#define BN 64
#define QK_STR 129
#define PS_STR 68

__global__ void __launch_bounds__(256) attn_kernel(
    const float* __restrict__ Q, const float* __restrict__ K,
    const float* __restrict__ V, float* __restrict__ Oa,
    const int* __restrict__ ctxp, const int* __restrict__ nseqp)
{
    extern __shared__ float sm[];
    float* Qs = sm;                           // BM * 129
    float* Ks = Qs + BM * QK_STR;             // BN * 129
    float* Ps = Ks + BN * QK_STR;             // BM * 68
    float* Vs = Ps + BM * PS_STR;             // BN * 128

    const int tid = threadIdx.x;
    const int tx  = tid & 15;
    const int ty  = tid >> 4;
    const int q0  = blockIdx.x * BM;
    const int h   = blockIdx.y;
    const int b   = blockIdx.z;
    const int hist = (S_ - ctxp[0]) / nseqp[0];

    const float scale = 0.08838834764831845f;   // 1/sqrt(128)

    // Load Q tile (pre-scaled) into padded smem rows.
    const float* Qg = Q + (size_t)(b * S_ + q0) * D_ + h * HD_;
    #pragma unroll
    for (int i = 0; i < 8; i++) {
        int f  = tid + i * 256;                // 2048 float4s
        int r  = f >> 5;
        int c4 = (f & 31) * 4;
        float4 v = *(const float4*)(Qg + (size_t)r * D_ + c4);
        float* dst = Qs + r * QK_STR + c4;
        dst[0] = v.x * scale; dst[1] = v.y * scale;
        dst[2] = v.z * scale; dst[3] = v.w * scale;
    }

    float m[4], l[4], o[4][8];
    int kvlen[4];
    #pragma unroll
    for (int i = 0; i < 4; i++) {
        m[i] = -1e30f; l[i] = 0.0f;
        #pragma unroll
        for (int d = 0; d < 8; d++) o[i][d] = 0.0f;
        const int sq = q0 + ty * 4 + i;
        kvlen[i] = (sq < hist) ? hist : S_;
    }
    const int kv_end = (q0 + BM - 1 < hist) ? hist : S_;

    const float* Kg = K + (size_t)b * S_ * D_ + h * HD_;
    const float* Vg = V + (size_t)b * S_ * D_ + h * HD_;

    for (int kt = 0; kt < kv_end; kt += BN) {
        __syncthreads();   // previous tile's PV done; smem free
        #pragma unroll
        for (int i = 0; i < 8; i++) {
            int f  = tid + i * 256;
            int r  = f >> 5;
            int c4 = (f & 31) * 4;
            float4 kv = *(const float4*)(Kg + (size_t)(kt + r) * D_ + c4);
            float* kd = Ks + r * QK_STR + c4;
            kd[0] = kv.x; kd[1] = kv.y; kd[2] = kv.z; kd[3] = kv.w;
            float4 vv = *(const float4*)(Vg + (size_t)(kt + r) * D_ + c4);
            *(float4*)(Vs + r * HD_ + c4) = vv;
        }
        __syncthreads();

        // S = Q K^T (64x64x128 SIMT GEMM)
        float sc[4][4];
        #pragma unroll
        for (int i = 0; i < 4; i++)
            #pragma unroll
            for (int j = 0; j < 4; j++) sc[i][j] = 0.0f;

        const float* qb = Qs + (ty * 4) * QK_STR;
        const float* kb = Ks + (tx * 4) * QK_STR;
        #pragma unroll 4
        for (int kk = 0; kk < HD_; kk++) {
            float qf[4], kf[4];
            #pragma unroll
            for (int i = 0; i < 4; i++) qf[i] = qb[i * QK_STR + kk];
            #pragma unroll
            for (int j = 0; j < 4; j++) kf[j] = kb[j * QK_STR + kk];
            #pragma unroll
            for (int i = 0; i < 4; i++)
                #pragma unroll
                for (int j = 0; j < 4; j++)
                    sc[i][j] = fmaf(qf[i], kf[j], sc[i][j]);
        }

        // per-row kv mask
        #pragma unroll
        for (int i = 0; i < 4; i++)
            #pragma unroll
            for (int j = 0; j < 4; j++)
                if (kt + tx * 4 + j >= kvlen[i]) sc[i][j] = -1e30f;

        // online softmax (row groups = 16 tx lanes, a half-warp)
        #pragma unroll
        for (int i = 0; i < 4; i++) {
            float mx = fmaxf(fmaxf(sc[i][0], sc[i][1]), fmaxf(sc[i][2], sc[i][3]));
            mx = fmaxf(mx, __shfl_xor_sync(0xffffffffu, mx, 1));
            mx = fmaxf(mx, __shfl_xor_sync(0xffffffffu, mx, 2));
            mx = fmaxf(mx, __shfl_xor_sync(0xffffffffu, mx, 4));
            mx = fmaxf(mx, __shfl_xor_sync(0xffffffffu, mx, 8));
            const float mn   = fmaxf(m[i], mx);
            const float corr = __expf(m[i] - mn);
            m[i] = mn;
            float p0 = __expf(sc[i][0] - mn);
            float p1 = __expf(sc[i][1] - mn);
            float p2 = __expf(sc[i][2] - mn);
            float p3 = __expf(sc[i][3] - mn);
            float psum = p0 + p1 + p2 + p3;
            psum += __shfl_xor_sync(0xffffffffu, psum, 1);
            psum += __shfl_xor_sync(0xffffffffu, psum, 2);
            psum += __shfl_xor_sync(0xffffffffu, psum, 4);
            psum += __shfl_xor_sync(0xffffffffu, psum, 8);
            l[i] = l[i] * corr + psum;
            #pragma unroll
            for (int d = 0; d < 8; d++) o[i][d] *= corr;
            float4 pv4 = {p0, p1, p2, p3};
            *(float4*)(Ps + (ty * 4 + i) * PS_STR + tx * 4) = pv4;
        }
        __syncthreads();   // P visible to everyone

        // O += P V  (64x128x64 SIMT GEMM)
        const float* pb = Ps + (ty * 4) * PS_STR;
        #pragma unroll 2
        for (int k = 0; k < BN; k++) {
            float4 v0 = *(const float4*)(Vs + k * HD_ + tx * 8);
            float4 v1 = *(const float4*)(Vs + k * HD_ + tx * 8 + 4);
            #pragma unroll
            for (int i = 0; i < 4; i++) {
                const float p = pb[i * PS_STR + k];
                o[i][0] = fmaf(p, v0.x, o[i][0]);
                o[i][1] = fmaf(p, v0.y, o[i][1]);
                o[i][2] = fmaf(p, v0.z, o[i][2]);
                o[i][3] = fmaf(p, v0.w, o[i][3]);
                o[i][4] = fmaf(p, v1.x, o[i][4]);
                o[i][5] = fmaf(p, v1.y, o[i][5]);
                o[i][6] = fmaf(p, v1.z, o[i][6]);
                o[i][7] = fmaf(p, v1.w, o[i][7]);
            }
        }
    }

    // epilogue: O /= l, write (b, s, h, hd)
    float* Og = Oa + (size_t)(b * S_ + q0 + ty * 4) * D_ + h * HD_ + tx * 8;
    #pragma unroll
    for (int i = 0; i < 4; i++) {
        const float inv = 1.0f / l[i];
        float4 r0 = {o[i][0] * inv, o[i][1] * inv, o[i][2] * inv, o[i][3] * inv};
        float4 r1 = {o[i][4] * inv, o[i][5] * inv, o[i][6] * inv, o[i][7] * inv};
        *(float4*)(Og + (size_t)i * D_)     = r0;
        *(float4*)(Og + (size_t)i * D_ + 4) = r1;
    }
}

// ---------------------------------------------------------------------------
// kernel_launch
// ---------------------------------------------------------------------------
extern "C" void kernel_launch(void* const* d_in, const int* in_sizes, int n_in,
                              void* d_out, int out_size)
{
    const float* hidden = (const float*)d_in[0];
    const float* rot    = (const float*)d_in[1];
    const float* Wq = (const float*)d_in[2];
    const float* bq = (const float*)d_in[3];
    const float* Wk = (const float*)d_in[4];
    const float* bk = (const float*)d_in[5];
    const float* Wv = (const float*)d_in[6];
    const float* bv = (const float*)d_in[7];
    const float* gq = (const float*)d_in[8];
    const float* gk = (const float*)d_in[9];
    const float* Wo = (const float*)d_in[10];
    const float* bo = (const float*)d_in[11];
    const int*   ctx  = (const int*)d_in[12];
    const int*   nseq = (const int*)d_in[13];
    float* out = (float*)d_out;

    float *q, *k, *v, *a;
    cudaGetSymbolAddress((void**)&q, g_q);
    cudaGetSymbolAddress((void**)&k, g_k);
    cudaGetSymbolAddress((void**)&v, g_v);
    cudaGetSymbolAddress((void**)&a, g_attn);

    const dim3 gemm_grid(D_ / 128, M_ / 128);   // (16, 48)

    // QKV projections
    gemm_bias<<<gemm_grid, 256>>>(hidden, Wq, bq, q);
    gemm_bias<<<gemm_grid, 256>>>(hidden, Wk, bk, k);
    gemm_bias<<<gemm_grid, 256>>>(hidden, Wv, bv, v);

    // RMSNorm + RoPE on q and k (in place)
    rms_rope<<<dim3(M_, 2), 256>>>(q, k, gq, gk, rot);

    // Attention
    const int smem_bytes = (BM * QK_STR + BN * QK_STR + BM * PS_STR + BN * HD_) * 4;
    cudaFuncSetAttribute(attn_kernel, cudaFuncAttributeMaxDynamicSharedMemorySize,
                         smem_bytes);
    attn_kernel<<<dim3(S_ / BM, H_, B_), 256, smem_bytes>>>(q, k, v, a, ctx, nseq);

    // Output projection -> d_out
    gemm_bias<<<gemm_grid, 256>>>(a, Wo, bo, out);
}

// round 2
// speedup vs baseline: 1.1480x; 1.1480x over previous
#include <cuda_runtime.h>
#include <cuda_bf16.h>
#include <cstdint>

// Problem constants (shapes fixed by the dataset).
#define B_   2
#define S_   3072
#define D_   2048
#define H_   16
#define HD_  128
#define M_   (B_ * S_)     // 6144 tokens

// ---------------------------------------------------------------------------
// Scratch (static device globals; no allocation anywhere)
// ---------------------------------------------------------------------------
__device__ float g_q[M_ * D_];
__device__ float g_k[M_ * D_];
__device__ float g_v[M_ * D_];
__device__ float g_attn[M_ * D_];

// ---------------------------------------------------------------------------
// tf32 helpers
// ---------------------------------------------------------------------------
__device__ __forceinline__ uint32_t f2tf32(float x) {
    uint32_t r;
    asm("cvt.rna.tf32.f32 %0, %1;" : "=r"(r) : "f"(x));
    return r;
}
__device__ __forceinline__ void split_tf32(float x, uint32_t& hi, uint32_t& lo) {
    hi = f2tf32(x);
    float r = x - __uint_as_float(hi);
    lo = f2tf32(r);
}
__device__ __forceinline__ void mma_tf32(float c[4], const uint32_t a[4],
                                         const uint32_t b[2]) {
    asm volatile(
        "mma.sync.aligned.m16n8k8.row.col.f32.tf32.tf32.f32 "
        "{%0,%1,%2,%3}, {%4,%5,%6,%7}, {%8,%9}, {%0,%1,%2,%3};"
        : "+f"(c[0]), "+f"(c[1]), "+f"(c[2]), "+f"(c[3])
        : "r"(a[0]), "r"(a[1]), "r"(a[2]), "r"(a[3]), "r"(b[0]), "r"(b[1]));
}

// ---------------------------------------------------------------------------
// GEMM (3xTF32 tensor-core):  O[m,n] = sum_k X[m,k] * W[n,k] + bias[n]
// X: (M_, 2048) row-major, W: (2048, 2048) row-major, O: (M_, 2048)
// Block tile 128x128, BK=32, 256 threads = 8 warps (2x4), warp tile 64x32.
// smem planes: A_hi, A_lo, B_hi, B_lo, each 128 rows x stride 36 (padded).
// ---------------------------------------------------------------------------
#define GBK   32
#define GSTR  36
#define GPLANE (128 * GSTR)
#define GEMM_SMEM (4 * GPLANE * 4)   // bytes = 73728

__global__ void __launch_bounds__(256, 1) gemm_tf32(
    const float* __restrict__ X,
    const float* __restrict__ W,
    const float* __restrict__ bias,
    float*       __restrict__ O)
{
    extern __shared__ uint32_t gsm[];
    uint32_t* Ah = gsm;
    uint32_t* Al = gsm + GPLANE;
    uint32_t* Bh = gsm + 2 * GPLANE;
    uint32_t* Bl = gsm + 3 * GPLANE;

    const int bm   = blockIdx.y * 128;
    const int bn   = blockIdx.x * 128;
    const int tid  = threadIdx.x;
    const int warp = tid >> 5;
    const int lane = tid & 31;
    const int lr   = lane >> 2;   // 0..7
    const int lc   = lane & 3;    // 0..3
    const int wm   = (warp & 1) * 64;   // 2 warps along M
    const int wn   = (warp >> 1) * 32;  // 4 warps along N

    // global-load mapping: each thread loads 4 float4 of A and 4 of B per tile
    const int grow = tid >> 3;          // 0..31
    const int gcol = (tid & 7) * 4;     // 0,4,...,28

    float acc[4][4][4];
    #pragma unroll
    for (int mi = 0; mi < 4; mi++)
        #pragma unroll
        for (int ni = 0; ni < 4; ni++)
            #pragma unroll
            for (int r = 0; r < 4; r++) acc[mi][ni][r] = 0.0f;

    float4 ra[4], rb[4];
    #pragma unroll
    for (int i = 0; i < 4; i++) {
        ra[i] = *(const float4*)(X + (size_t)(bm + grow + i * 32) * D_ + gcol);
        rb[i] = *(const float4*)(W + (size_t)(bn + grow + i * 32) * D_ + gcol);
    }

    for (int kt = 0; kt < D_; kt += GBK) {
        __syncthreads();   // previous tile fully consumed
        #pragma unroll
        for (int i = 0; i < 4; i++) {
            const int base = (grow + i * 32) * GSTR + gcol;
            uint4 h, l;
            split_tf32(ra[i].x, h.x, l.x);
            split_tf32(ra[i].y, h.y, l.y);
            split_tf32(ra[i].z, h.z, l.z);
            split_tf32(ra[i].w, h.w, l.w);
            *(uint4*)(Ah + base) = h;
            *(uint4*)(Al + base) = l;
            split_tf32(rb[i].x, h.x, l.x);
            split_tf32(rb[i].y, h.y, l.y);
            split_tf32(rb[i].z, h.z, l.z);
            split_tf32(rb[i].w, h.w, l.w);
            *(uint4*)(Bh + base) = h;
            *(uint4*)(Bl + base) = l;
        }
        __syncthreads();

        if (kt + GBK < D_) {
            #pragma unroll
            for (int i = 0; i < 4; i++) {
                ra[i] = *(const float4*)(X + (size_t)(bm + grow + i * 32) * D_ +
                                         kt + GBK + gcol);
                rb[i] = *(const float4*)(W + (size_t)(bn + grow + i * 32) * D_ +
                                         kt + GBK + gcol);
            }
        }

        #pragma unroll
        for (int kk = 0; kk < GBK; kk += 8) {
            uint32_t ah[4][4], al[4][4], bh[4][2], bl[4][2];
            #pragma unroll
            for (int mi = 0; mi < 4; mi++) {
                const int r0 = (wm + mi * 16 + lr) * GSTR + kk + lc;
                ah[mi][0] = Ah[r0];
                ah[mi][1] = Ah[r0 + 8 * GSTR];
                ah[mi][2] = Ah[r0 + 4];
                ah[mi][3] = Ah[r0 + 8 * GSTR + 4];
                al[mi][0] = Al[r0];
                al[mi][1] = Al[r0 + 8 * GSTR];
                al[mi][2] = Al[r0 + 4];
                al[mi][3] = Al[r0 + 8 * GSTR + 4];
            }
            #pragma unroll
            for (int ni = 0; ni < 4; ni++) {
                const int r0 = (wn + ni * 8 + lr) * GSTR + kk + lc;
                bh[ni][0] = Bh[r0];
                bh[ni][1] = Bh[r0 + 4];
                bl[ni][0] = Bl[r0];
                bl[ni][1] = Bl[r0 + 4];
            }
            #pragma unroll
            for (int mi = 0; mi < 4; mi++)
                #pragma unroll
                for (int ni = 0; ni < 4; ni++) {
                    mma_tf32(acc[mi][ni], ah[mi], bh[ni]);
                    mma_tf32(acc[mi][ni], al[mi], bh[ni]);
                    mma_tf32(acc[mi][ni], ah[mi], bl[ni]);
                }
        }
    }

    // epilogue: acc + bias -> O
    #pragma unroll
    for (int ni = 0; ni < 4; ni++) {
        const int c = bn + wn + ni * 8 + 2 * lc;
        const float b0 = __ldg(bias + c);
        const float b1 = __ldg(bias + c + 1);
        #pragma unroll
        for (int mi = 0; mi < 4; mi++) {
            const int r = bm + wm + mi * 16 + lr;
            float2 v0 = {acc[mi][ni][0] + b0, acc[mi][ni][1] + b1};
            float2 v1 = {acc[mi][ni][2] + b0, acc[mi][ni][3] + b1};
            *(float2*)(O + (size_t)r * D_ + c)       = v0;
            *(float2*)(O + (size_t)(r + 8) * D_ + c) = v1;
        }
    }
}

// ---------------------------------------------------------------------------
// Fused RMSNorm + interleaved RoPE, in place, for Q (blockIdx.y==0) and K (==1)
// ---------------------------------------------------------------------------
__global__ void __launch_bounds__(256) rms_rope(
    float* __restrict__ Tq, float* __restrict__ Tk,
    const float* __restrict__ gq, const float* __restrict__ gk,
    const float* __restrict__ rot)
{
    const int token = blockIdx.x;        // b*S + s
    const int s     = token % S_;
    float*       T  = (blockIdx.y == 0) ? Tq : Tk;
    const float* g  = (blockIdx.y == 0) ? gq : gk;
    const int t     = threadIdx.x;

    float* row = T + (size_t)token * D_;
    float4 v0 = *(const float4*)(row + t * 8);
    float4 v1 = *(const float4*)(row + t * 8 + 4);
    float x[8] = {v0.x, v0.y, v0.z, v0.w, v1.x, v1.y, v1.z, v1.w};

    float ss = 0.0f;
    #pragma unroll
    for (int i = 0; i < 8; i++) ss += x[i] * x[i];
    #pragma unroll
    for (int o = 16; o; o >>= 1) ss += __shfl_xor_sync(0xffffffffu, ss, o);

    __shared__ float red[8];
    __shared__ float rs_s;
    if ((t & 31) == 0) red[t >> 5] = ss;
    __syncthreads();
    if (t == 0) {
        float tot = 0.0f;
        #pragma unroll
        for (int i = 0; i < 8; i++) tot += red[i];
        rs_s = rsqrtf(tot * (1.0f / (float)D_) + 1e-6f);
    }
    __syncthreads();
    const float rs = rs_s;

    const float* rc = rot + (size_t)s * (2 * HD_);
    float out[8];
    #pragma unroll
    for (int j = 0; j < 4; j++) {
        const int d0 = t * 8 + 2 * j;          // even dim
        const int i2 = d0 & (HD_ - 1);         // 2*i within the head
        const float c  = rc[i2];               // cos[2i]
        const float sn = rc[HD_ + i2 + 1];     // sin[2i+1]
        const float x1 = x[2 * j]     * rs * g[d0];
        const float x2 = x[2 * j + 1] * rs * g[d0 + 1];
        out[2 * j]     = x1 * c - x2 * sn;
        out[2 * j + 1] = x1 * sn + x2 * c;
    }
    float4 o0 = {out[0], out[1], out[2], out[3]};
    float4 o1 = {out[4], out[5], out[6], out[7]};
    *(float4*)(row + t * 8)     = o0;
    *(float4*)(row + t * 8 + 4) = o1;
}

// ---------------------------------------------------------------------------
// Flash-style SDPA, fp32 SIMT (unchanged this round).
// ---------------------------------------------------------------------------
#define BM 64
#define BN 64
#define QK_STR 129
#define PS_STR 68

__global__ void __launch_bounds__(256) attn_kernel(
    const float* __restrict__ Q, const float* __restrict__ K,
    const float* __restrict__ V, float* __restrict__ Oa,
    const int* __restrict__ ctxp, const int* __restrict__ nseqp)
{
    extern __shared__ float sm[];
    float* Qs = sm;                           // BM * 129
    float* Ks = Qs + BM * QK_STR;             // BN * 129
    float* Ps = Ks + BN * QK_STR;             // BM * 68
    float* Vs = Ps + BM * PS_STR;             // BN * 128

    const int tid = threadIdx.x;
    const int tx  = tid & 15;
    const int ty  = tid >> 4;
    const int q0  = blockIdx.x * BM;
    const int h   = blockIdx.y;
    const int b   = blockIdx.z;
    const int hist = (S_ - ctxp[0]) / nseqp[0];

    const float scale = 0.08838834764831845f;   // 1/sqrt(128)

    const float* Qg = Q + (size_t)(b * S_ + q0) * D_ + h * HD_;
    #pragma unroll
    for (int i = 0; i < 8; i++) {
        int f  = tid + i * 256;                // 2048 float4s
        int r  = f >> 5;
        int c4 = (f & 31) * 4;
        float4 v = *(const float4*)(Qg + (size_t)r * D_ + c4);
        float* dst = Qs + r * QK_STR + c4;
        dst[0] = v.x * scale; dst[1] = v.y * scale;
        dst[2] = v.z * scale; dst[3] = v.w * scale;
    }

    float m[4], l[4], o[4][8];
    int kvlen[4];
    #pragma unroll
    for (int i = 0; i < 4; i++) {
        m[i] = -1e30f; l[i] = 0.0f;
        #pragma unroll
        for (int d = 0; d < 8; d++) o[i][d] = 0.0f;
        const int sq = q0 + ty * 4 + i;
        kvlen[i] = (sq < hist) ? hist : S_;
    }
    const int kv_end = (q0 + BM - 1 < hist) ? hist : S_;

    const float* Kg = K + (size_t)b * S_ * D_ + h * HD_;
    const float* Vg = V + (size_t)b * S_ * D_ + h * HD_;

    for (int kt = 0; kt < kv_end; kt += BN) {
        __syncthreads();
        #pragma unroll
        for (int i = 0; i < 8; i++) {
            int f  = tid + i * 256;
            int r  = f >> 5;
            int c4 = (f & 31) * 4;
            float4 kv = *(const float4*)(Kg + (size_t)(kt + r) * D_ + c4);
            float* kd = Ks + r * QK_STR + c4;
            kd[0] = kv.x; kd[1] = kv.y; kd[2] = kv.z; kd[3] = kv.w;
            float4 vv = *(const float4*)(Vg + (size_t)(kt + r) * D_ + c4);
            *(float4*)(Vs + r * HD_ + c4) = vv;
        }
        __syncthreads();

        float sc[4][4];
        #pragma unroll
        for (int i = 0; i < 4; i++)
            #pragma unroll
            for (int j = 0; j < 4; j++) sc[i][j] = 0.0f;

        const float* qb = Qs + (ty * 4) * QK_STR;
        const float* kb = Ks + (tx * 4) * QK_STR;
        #pragma unroll 4
        for (int kk = 0; kk < HD_; kk++) {
            float qf[4], kf[4];
            #pragma unroll
            for (int i = 0; i < 4; i++) qf[i] = qb[i * QK_STR + kk];
            #pragma unroll
            for (int j = 0; j < 4; j++) kf[j] = kb[j * QK_STR + kk];
            #pragma unroll
            for (int i = 0; i < 4; i++)
                #pragma unroll
                for (int j = 0; j < 4; j++)
                    sc[i][j] = fmaf(qf[i], kf[j], sc[i][j]);
        }

        #pragma unroll
        for (int i = 0; i < 4; i++)
            #pragma unroll
            for (int j = 0; j < 4; j++)
                if (kt + tx * 4 + j >= kvlen[i]) sc[i][j] = -1e30f;

        #pragma unroll
        for (int i = 0; i < 4; i++) {
            float mx = fmaxf(fmaxf(sc[i][0], sc[i][1]), fmaxf(sc[i][2], sc[i][3]));
            mx = fmaxf(mx, __shfl_xor_sync(0xffffffffu, mx, 1));
            mx = fmaxf(mx, __shfl_xor_sync(0xffffffffu, mx, 2));
            mx = fmaxf(mx, __shfl_xor_sync(0xffffffffu, mx, 4));
            mx = fmaxf(mx, __shfl_xor_sync(0xffffffffu, mx, 8));
            const float mn   = fmaxf(m[i], mx);
            const float corr = __expf(m[i] - mn);
            m[i] = mn;
            float p0 = __expf(sc[i][0] - mn);
            float p1 = __expf(sc[i][1] - mn);
            float p2 = __expf(sc[i][2] - mn);
            float p3 = __expf(sc[i][3] - mn);
            float psum = p0 + p1 + p2 + p3;
            psum += __shfl_xor_sync(0xffffffffu, psum, 1);
            psum += __shfl_xor_sync(0xffffffffu, psum, 2);
            psum += __shfl_xor_sync(0xffffffffu, psum, 4);
            psum += __shfl_xor_sync(0xffffffffu, psum, 8);
            l[i] = l[i] * corr + psum;
            #pragma unroll
            for (int d = 0; d < 8; d++) o[i][d] *= corr;
            float4 pv4 = {p0, p1, p2, p3};
            *(float4*)(Ps + (ty * 4 + i) * PS_STR + tx * 4) = pv4;
        }
        __syncthreads();

        const float* pb = Ps + (ty * 4) * PS_STR;
        #pragma unroll 2
        for (int k = 0; k < BN; k++) {
            float4 v0 = *(const float4*)(Vs + k * HD_ + tx * 8);
            float4 v1 = *(const float4*)(Vs + k * HD_ + tx * 8 + 4);
            #pragma unroll
            for (int i = 0; i < 4; i++) {
                const float p = pb[i * PS_STR + k];
                o[i][0] = fmaf(p, v0.x, o[i][0]);
                o[i][1] = fmaf(p, v0.y, o[i][1]);
                o[i][2] = fmaf(p, v0.z, o[i][2]);
                o[i][3] = fmaf(p, v0.w, o[i][3]);
                o[i][4] = fmaf(p, v1.x, o[i][4]);
                o[i][5] = fmaf(p, v1.y, o[i][5]);
                o[i][6] = fmaf(p, v1.z, o[i][6]);
                o[i][7] = fmaf(p, v1.w, o[i][7]);
            }
        }
    }

    float* Og = Oa + (size_t)(b * S_ + q0 + ty * 4) * D_ + h * HD_ + tx * 8;
    #pragma unroll
    for (int i = 0; i < 4; i++) {
        const float inv = 1.0f / l[i];
        float4 r0 = {o[i][0] * inv, o[i][1] * inv, o[i][2] * inv, o[i][3] * inv};
        float4 r1 = {o[i][4] * inv, o[i][5] * inv, o[i][6] * inv, o[i][7] * inv};
        *(float4*)(Og + (size_t)i * D_)     = r0;
        *(float4*)(Og + (size_t)i * D_ + 4) = r1;
    }
}

// ---------------------------------------------------------------------------
// kernel_launch
// ---------------------------------------------------------------------------
extern "C" void kernel_launch(void* const* d_in, const int* in_sizes, int n_in,
                              void* d_out, int out_size)
{
    const float* hidden = (const float*)d_in[0];
    const float* rot    = (const float*)d_in[1];
    const float* Wq = (const float*)d_in[2];
    const float* bq = (const float*)d_in[3];
    const float* Wk = (const float*)d_in[4];
    const float* bk = (const float*)d_in[5];
    const float* Wv = (const float*)d_in[6];
    const float* bv = (const float*)d_in[7];
    const float* gq = (const float*)d_in[8];
    const float* gk = (const float*)d_in[9];
    const float* Wo = (const float*)d_in[10];
    const float* bo = (const float*)d_in[11];
    const int*   ctx  = (const int*)d_in[12];
    const int*   nseq = (const int*)d_in[13];
    float* out = (float*)d_out;

    float *q, *k, *v, *a;
    cudaGetSymbolAddress((void**)&q, g_q);
    cudaGetSymbolAddress((void**)&k, g_k);
    cudaGetSymbolAddress((void**)&v, g_v);
    cudaGetSymbolAddress((void**)&a, g_attn);

    cudaFuncSetAttribute(gemm_tf32, cudaFuncAttributeMaxDynamicSharedMemorySize,
                         GEMM_SMEM);

    const dim3 gemm_grid(D_ / 128, M_ / 128);   // (16, 48)

    // QKV projections (3xTF32 tensor cores)
    gemm_tf32<<<gemm_grid, 256, GEMM_SMEM>>>(hidden, Wq, bq, q);
    gemm_tf32<<<gemm_grid, 256, GEMM_SMEM>>>(hidden, Wk, bk, k);
    gemm_tf32<<<gemm_grid, 256, GEMM_SMEM>>>(hidden, Wv, bv, v);

    // RMSNorm + RoPE on q and k (in place)
    rms_rope<<<dim3(M_, 2), 256>>>(q, k, gq, gk, rot);

    // Attention
    const int smem_bytes = (BM * QK_STR + BN * QK_STR + BM * PS_STR + BN * HD_) * 4;
    cudaFuncSetAttribute(attn_kernel, cudaFuncAttributeMaxDynamicSharedMemorySize,
                         smem_bytes);
    attn_kernel<<<dim3(S_ / BM, H_, B_), 256, smem_bytes>>>(q, k, v, a, ctx, nseq);

    // Output projection -> d_out
    gemm_tf32<<<gemm_grid, 256, GEMM_SMEM>>>(a, Wo, bo, out);
}